// round 1
// baseline (speedup 1.0000x reference)
#include <cuda_runtime.h>
#include <cuda_bf16.h>

#define NB      8192
#define STEPS   50
#define HID     64

// Scratch for nearest-neighbor c0 values (no cudaMalloc allowed).
__device__ float g_c0[NB];

// ---------------------------------------------------------------------------
// Kernel 1: 1-D nearest neighbor (excluding self, first-index tie break).
// c is [B,1] -> distance = |c_i - c_j|; diagonal forced to 1e9 like reference.
// Stage c in shared memory; each thread scans all B.
// ---------------------------------------------------------------------------
__global__ void __launch_bounds__(256) nn_kernel(const float* __restrict__ c, int B)
{
    extern __shared__ float sc[];
    for (int j = threadIdx.x; j < B; j += blockDim.x) sc[j] = c[j];
    __syncthreads();

    int i = blockIdx.x * blockDim.x + threadIdx.x;
    if (i >= B) return;
    float ci = sc[i];
    float best = 3.0e38f;
    int bj = 0;
    for (int j = 0; j < B; ++j) {
        float d = fabsf(ci - sc[j]);
        if (j == i) d = 1.0e9f;           // matches dists + eye*1e9
        if (d < best) { best = d; bj = j; }  // strict < keeps first index (argmin)
    }
    g_c0[i] = sc[bj];
}

// ---------------------------------------------------------------------------
// Kernel 2: per-sample 50-step inner solve.
//
// Layout: thread pair (lanes 2s, 2s+1 of a warp) = one sample; each lane owns
// half (32) of the 64-wide reduction dimension of every matvec. The 64 output
// accumulators are fully unrolled register arrays; weight rows are read as
// warp-uniform LDS.128 (2 distinct addresses/warp -> broadcast, crossbar-free).
// Partial sums are combined with __shfl_xor_sync(.,1); both lanes then hold
// bit-identical full values (float add is commutative), so y stays in sync
// without further communication.
//
// Math per step (JVP term has zero y-gradient, see analysis):
//   z1 = a1 + y*w1y                (a1 = W1[:,0]x + W1[:,2]c0 + b1)
//   z2 = W2 relu(z1) + b2 ; m2
//   z3 = W3 relu(z2) + b3 ; m3
//   A  = W3^T (m3 .* W4)
//   t  = W2  (m1 .* w1y)
//   gy = sum_o m2[o] * A[o] * t[o]
//   y  = y - 0.1*gy   (non-fused mul+sub to mirror JAX rounding)
// ---------------------------------------------------------------------------
__global__ void __launch_bounds__(128, 1) solve_kernel(
    const float* __restrict__ x,
    const float* __restrict__ W1, const float* __restrict__ b1,
    const float* __restrict__ W2, const float* __restrict__ b2,
    const float* __restrict__ W3, const float* __restrict__ b3,
    const float* __restrict__ W4,
    float* __restrict__ out)
{
    // sW2t[k*64+o] = W2[o][k]  (forward layer2 + t-accumulation)
    // sW3t[k*64+o] = W3[o][k]  (forward layer3)
    // sW3o[j*64+o] = W3[j][o]  (backward A-accumulation, row-contiguous)
    __shared__ float sW2t[HID * HID];
    __shared__ float sW3t[HID * HID];
    __shared__ float sW3o[HID * HID];
    __shared__ float sB2[HID], sB3[HID], sW4[HID];

    const int tid = threadIdx.x;
    for (int idx = tid; idx < HID * HID; idx += 128) {
        int o = idx >> 6, k = idx & 63;
        float w2 = W2[idx];
        float w3 = W3[idx];
        sW2t[k * HID + o] = w2;
        sW3t[k * HID + o] = w3;
        sW3o[idx] = w3;
    }
    if (tid < HID) { sB2[tid] = b2[tid]; sB3[tid] = b3[tid]; sW4[tid] = W4[tid]; }
    __syncthreads();

    const int gt    = blockIdx.x * 128 + tid;
    const int s     = gt >> 1;       // sample id
    const int half  = gt & 1;        // which 32-wide half of the reduction dim
    const int kbase = half << 5;

    const float xi  = x[s];
    const float c0i = g_c0[s];

    // Per-lane slice of layer-1 affine pieces (local mem, rolled-index access).
    float a1l[32], w1yl[32];
    #pragma unroll 1
    for (int kk = 0; kk < 32; ++kk) {
        int o = kbase + kk;
        a1l[kk]  = __fmaf_rn(W1[o * 3 + 0], xi, __fmaf_rn(W1[o * 3 + 2], c0i, b1[o]));
        w1yl[kk] = W1[o * 3 + 1];
    }

    float y = 0.0f;   // Y_MEAN
    float h2l[HID];   // local (dynamic kbase+kk indexing)

    for (int step = 0; step < STEPS; ++step) {
        float acc[HID];

        // ---------- forward layer 2 ----------
        #pragma unroll
        for (int o = 0; o < HID; ++o) acc[o] = 0.0f;
        #pragma unroll 1
        for (int kk = 0; kk < 32; ++kk) {
            float z1 = __fmaf_rn(y, w1yl[kk], a1l[kk]);
            float h1 = (z1 > 0.0f) ? z1 : 0.0f;
            const float* wr = &sW2t[(kbase + kk) * HID];
            #pragma unroll
            for (int o = 0; o < HID; ++o) acc[o] = __fmaf_rn(wr[o], h1, acc[o]);
        }
        unsigned m2lo = 0u, m2hi = 0u;
        #pragma unroll
        for (int o = 0; o < HID; ++o) {
            float z = acc[o] + __shfl_xor_sync(0xffffffffu, acc[o], 1) + sB2[o];
            float h = (z > 0.0f) ? z : 0.0f;
            h2l[o] = h;
            unsigned bit = (z > 0.0f) ? 1u : 0u;
            if (o < 32) m2lo |= bit << o; else m2hi |= bit << (o - 32);
        }

        // ---------- forward layer 3 (only masks needed downstream) ----------
        #pragma unroll
        for (int o = 0; o < HID; ++o) acc[o] = 0.0f;
        #pragma unroll 1
        for (int kk = 0; kk < 32; ++kk) {
            float hk = h2l[kbase + kk];
            const float* wr = &sW3t[(kbase + kk) * HID];
            #pragma unroll
            for (int o = 0; o < HID; ++o) acc[o] = __fmaf_rn(wr[o], hk, acc[o]);
        }
        unsigned m3lo = 0u, m3hi = 0u;
        #pragma unroll
        for (int o = 0; o < HID; ++o) {
            float z = acc[o] + __shfl_xor_sync(0xffffffffu, acc[o], 1) + sB3[o];
            unsigned bit = (z > 0.0f) ? 1u : 0u;
            if (o < 32) m3lo |= bit << o; else m3hi |= bit << (o - 32);
        }

        // ---------- backward: A = W3^T (m3.*W4), t = W2 (m1.*w1y) ----------
        const unsigned myM3 = half ? m3hi : m3lo;
        float tarr[HID];
        #pragma unroll
        for (int o = 0; o < HID; ++o) { acc[o] = 0.0f; tarr[o] = 0.0f; }
        #pragma unroll 1
        for (int kk = 0; kk < 32; ++kk) {
            int j = kbase + kk;
            float v3 = ((myM3 >> kk) & 1u) ? sW4[j] : 0.0f;
            float z1 = __fmaf_rn(y, w1yl[kk], a1l[kk]);
            float mw = (z1 > 0.0f) ? w1yl[kk] : 0.0f;
            const float* w3r = &sW3o[j * HID];
            const float* w2r = &sW2t[j * HID];
            #pragma unroll
            for (int o = 0; o < HID; ++o) {
                acc[o]  = __fmaf_rn(w3r[o], v3, acc[o]);
                tarr[o] = __fmaf_rn(w2r[o], mw, tarr[o]);
            }
        }

        // ---------- gy = sum_o m2[o] * A[o] * t[o], 4-way ILP ----------
        float g0 = 0.0f, g1 = 0.0f, g2 = 0.0f, g3 = 0.0f;
        #pragma unroll
        for (int o = 0; o < HID; ++o) {
            float af = acc[o]  + __shfl_xor_sync(0xffffffffu, acc[o], 1);
            float tf = tarr[o] + __shfl_xor_sync(0xffffffffu, tarr[o], 1);
            unsigned bit = (o < 32) ? ((m2lo >> o) & 1u) : ((m2hi >> (o - 32)) & 1u);
            float vf = bit ? af : 0.0f;
            float p  = __fmul_rn(vf, tf);
            if ((o & 3) == 0)      g0 = __fadd_rn(g0, p);
            else if ((o & 3) == 1) g1 = __fadd_rn(g1, p);
            else if ((o & 3) == 2) g2 = __fadd_rn(g2, p);
            else                   g3 = __fadd_rn(g3, p);
        }
        float gy = __fadd_rn(__fadd_rn(g0, g1), __fadd_rn(g2, g3));

        // y <- y - 0.1*gy  (explicit mul then add: match JAX non-fused rounding)
        y = __fadd_rn(y, -__fmul_rn(0.1f, gy));
    }

    if (!half) out[s] = y;
}

// ---------------------------------------------------------------------------
// Launch: inputs per metadata order:
//   0:x [B] 1:c [B] 2:W1 [64*3] 3:b1 [64] 4:W2 [64*64] 5:b2 [64]
//   6:W3 [64*64] 7:b3 [64] 8:W4 [64] 9:b4 [1] (unused: gy independent of b4)
// ---------------------------------------------------------------------------
extern "C" void kernel_launch(void* const* d_in, const int* in_sizes, int n_in,
                              void* d_out, int out_size)
{
    const float* x  = (const float*)d_in[0];
    const float* c  = (const float*)d_in[1];
    const float* W1 = (const float*)d_in[2];
    const float* b1 = (const float*)d_in[3];
    const float* W2 = (const float*)d_in[4];
    const float* b2 = (const float*)d_in[5];
    const float* W3 = (const float*)d_in[6];
    const float* b3 = (const float*)d_in[7];
    const float* W4 = (const float*)d_in[8];
    float* out = (float*)d_out;

    const int B = in_sizes[0];   // 8192

    // 1) nearest neighbor -> g_c0
    {
        int threads = 256;
        int blocks  = (B + threads - 1) / threads;
        size_t smem = (size_t)B * sizeof(float);
        nn_kernel<<<blocks, threads, smem>>>(c, B);
    }

    // 2) 50-step inner solve: 2 lanes per sample, 128 threads per block
    {
        int total_threads = 2 * B;          // 16384
        int threads = 128;
        int blocks  = total_threads / threads;  // 128
        solve_kernel<<<blocks, threads>>>(x, W1, b1, W2, b2, W3, b3, W4, out);
    }
}

// round 2
// speedup vs baseline: 9.8969x; 9.8969x over previous
#include <cuda_runtime.h>
#include <cuda_bf16.h>

#define NB      8192
#define STEPS   50
#define HID     64

// Scratch for nearest-neighbor c0 values (no cudaMalloc allowed).
__device__ float g_c0[NB];

// ---------------------------------------------------------------------------
// Kernel 1: 1-D nearest neighbor (excluding self, first-index tie break).
// ---------------------------------------------------------------------------
__global__ void __launch_bounds__(256) nn_kernel(const float* __restrict__ c, int B)
{
    extern __shared__ float sc[];
    for (int j = threadIdx.x; j < B; j += blockDim.x) sc[j] = c[j];
    __syncthreads();

    int i = blockIdx.x * blockDim.x + threadIdx.x;
    if (i >= B) return;
    float ci = sc[i];
    float best = 3.0e38f;
    int bj = 0;
    for (int j = 0; j < B; ++j) {
        float d = fabsf(ci - sc[j]);
        if (j == i) d = 1.0e9f;            // matches dists + eye*1e9
        if (d < best) { best = d; bj = j; } // strict < keeps first index (argmin)
    }
    g_c0[i] = sc[bj];
}

// ---------------------------------------------------------------------------
// Kernel 2: warp-per-sample solve exploiting piecewise-linearity in y.
//
// E(x,y,c0) is piecewise-linear in y (ReLU net, linear head), so
// gy = dE/dy is piecewise-CONSTANT: it depends only on the masks (m1,m2,m3).
// Affine caching given masks:
//   z1 = a1 + y*w1y                                  (per-lane, 2 units)
//   u  = W2 (m1 .* a1),  t = W2 (m1 .* w1y)   -> z2 = u + y*t + b2
//   r  = W3 (m2 .* (u+b2)), s = W3 (m2 .* t)  -> z3 = r + y*s + b3
//   gy = sum_j m3[j] * W4[j] * s[j]
// (gy formula is algebraically identical to sum_o m2[o]*A[o]*t[o] of the
//  direct backprop: exchange the j/o sums.)
// The matvecs (u,t) recompute only when m1 changes; (r,s) when m1 or m2
// changes; gy when anything changed. Ballot results are warp-uniform, so
// all branches are warp-uniform (one warp == one sample, no divergence).
//
// Matvec: lane owns outputs l and l+32; weights in transposed smem with
// stride 65 (conflict-free lane-consecutive reads); activation reads are
// warp-uniform (broadcast, crossbar-free).
// ---------------------------------------------------------------------------
__global__ void __launch_bounds__(256) solve_kernel(
    const float* __restrict__ x,
    const float* __restrict__ W1, const float* __restrict__ b1,
    const float* __restrict__ W2, const float* __restrict__ b2,
    const float* __restrict__ W3, const float* __restrict__ b3,
    const float* __restrict__ W4,
    float* __restrict__ out, int B)
{
    __shared__ float sW2t[HID * 65];   // sW2t[k*65+o] = W2[o][k]
    __shared__ float sW3t[HID * 65];   // sW3t[k*65+o] = W3[o][k]
    __shared__ float sg1[8][HID];      // per-warp masked-activation scratch
    __shared__ float sg2[8][HID];

    const int tid = threadIdx.x;
    for (int idx = tid; idx < HID * HID; idx += 256) {
        int o = idx >> 6, k = idx & 63;
        sW2t[k * 65 + o] = W2[idx];
        sW3t[k * 65 + o] = W3[idx];
    }
    __syncthreads();

    const int w = tid >> 5;                 // warp in block
    const int l = tid & 31;                 // lane
    const int smp = blockIdx.x * 8 + w;     // sample id
    if (smp >= B) return;                   // whole warp exits together

    const int o0 = l, o1 = l + 32;          // hidden units owned by this lane

    const float xi  = x[smp];
    const float c0i = g_c0[smp];

    const float a1lo = __fmaf_rn(W1[o0 * 3 + 0], xi, __fmaf_rn(W1[o0 * 3 + 2], c0i, b1[o0]));
    const float a1hi = __fmaf_rn(W1[o1 * 3 + 0], xi, __fmaf_rn(W1[o1 * 3 + 2], c0i, b1[o1]));
    const float wylo = W1[o0 * 3 + 1];
    const float wyhi = W1[o1 * 3 + 1];
    const float b2lo = b2[o0], b2hi = b2[o1];
    const float b3lo = b3[o0], b3hi = b3[o1];
    const float w4lo = W4[o0], w4hi = W4[o1];

    float* g1 = sg1[w];
    float* g2 = sg2[w];

    float y = 0.0f;                         // Y_MEAN
    float u0 = 0.f, u1 = 0.f, t0 = 0.f, t1 = 0.f;
    float r0 = 0.f, r1 = 0.f, s0 = 0.f, s1 = 0.f;
    float gy = 0.0f;
    unsigned pm1lo = 0, pm1hi = 0, pm2lo = 0, pm2hi = 0, pm3lo = 0, pm3hi = 0;

    for (int step = 0; step < STEPS; ++step) {
        // ----- layer 1: z1 = a1 + y*w1y -----
        float z1lo = __fmaf_rn(y, wylo, a1lo);
        float z1hi = __fmaf_rn(y, wyhi, a1hi);
        unsigned m1lo = __ballot_sync(0xffffffffu, z1lo > 0.0f);
        unsigned m1hi = __ballot_sync(0xffffffffu, z1hi > 0.0f);
        bool c1 = (step == 0) | (m1lo != pm1lo) | (m1hi != pm1hi);
        if (c1) {
            pm1lo = m1lo; pm1hi = m1hi;
            __syncwarp();
            g1[o0] = (z1lo > 0.0f) ? a1lo : 0.0f;
            g1[o1] = (z1hi > 0.0f) ? a1hi : 0.0f;
            g2[o0] = (z1lo > 0.0f) ? wylo : 0.0f;
            g2[o1] = (z1hi > 0.0f) ? wyhi : 0.0f;
            __syncwarp();
            u0 = u1 = t0 = t1 = 0.0f;
            #pragma unroll 8
            for (int k = 0; k < HID; ++k) {
                float x1 = g1[k], x2 = g2[k];
                float wa = sW2t[k * 65 + o0];
                float wb = sW2t[k * 65 + o1];
                u0 = __fmaf_rn(wa, x1, u0);
                u1 = __fmaf_rn(wb, x1, u1);
                t0 = __fmaf_rn(wa, x2, t0);
                t1 = __fmaf_rn(wb, x2, t1);
            }
        }

        // ----- layer 2: z2 = u + y*t + b2 -----
        float z2lo = __fmaf_rn(y, t0, u0) + b2lo;
        float z2hi = __fmaf_rn(y, t1, u1) + b2hi;
        unsigned m2lo = __ballot_sync(0xffffffffu, z2lo > 0.0f);
        unsigned m2hi = __ballot_sync(0xffffffffu, z2hi > 0.0f);
        bool c2 = c1 | (m2lo != pm2lo) | (m2hi != pm2hi);
        if (c2) {
            pm2lo = m2lo; pm2hi = m2hi;
            __syncwarp();
            g1[o0] = (z2lo > 0.0f) ? (u0 + b2lo) : 0.0f;
            g1[o1] = (z2hi > 0.0f) ? (u1 + b2hi) : 0.0f;
            g2[o0] = (z2lo > 0.0f) ? t0 : 0.0f;
            g2[o1] = (z2hi > 0.0f) ? t1 : 0.0f;
            __syncwarp();
            r0 = r1 = s0 = s1 = 0.0f;
            #pragma unroll 8
            for (int k = 0; k < HID; ++k) {
                float x1 = g1[k], x2 = g2[k];
                float wa = sW3t[k * 65 + o0];
                float wb = sW3t[k * 65 + o1];
                r0 = __fmaf_rn(wa, x1, r0);
                r1 = __fmaf_rn(wb, x1, r1);
                s0 = __fmaf_rn(wa, x2, s0);
                s1 = __fmaf_rn(wb, x2, s1);
            }
        }

        // ----- layer 3: z3 = r + y*s + b3 ; gy = sum m3 .* W4 .* s -----
        float z3lo = __fmaf_rn(y, s0, r0) + b3lo;
        float z3hi = __fmaf_rn(y, s1, r1) + b3hi;
        unsigned m3lo = __ballot_sync(0xffffffffu, z3lo > 0.0f);
        unsigned m3hi = __ballot_sync(0xffffffffu, z3hi > 0.0f);
        bool c3 = c2 | (m3lo != pm3lo) | (m3hi != pm3hi);
        if (c3) {
            pm3lo = m3lo; pm3hi = m3hi;
            float p = ((z3lo > 0.0f) ? __fmul_rn(w4lo, s0) : 0.0f)
                    + ((z3hi > 0.0f) ? __fmul_rn(w4hi, s1) : 0.0f);
            #pragma unroll
            for (int off = 16; off; off >>= 1)
                p += __shfl_xor_sync(0xffffffffu, p, off);
            gy = p;    // identical on every lane (butterfly reduce)
        }

        // y <- y - 0.1*gy (non-fused to mirror JAX rounding)
        y = __fadd_rn(y, -__fmul_rn(0.1f, gy));
    }

    if (l == 0) out[smp] = y;
}

// ---------------------------------------------------------------------------
// Inputs (metadata order):
//   0:x [B] 1:c [B] 2:W1 [64*3] 3:b1 [64] 4:W2 [64*64] 5:b2 [64]
//   6:W3 [64*64] 7:b3 [64] 8:W4 [64] 9:b4 [1] (unused: gy independent of b4)
// ---------------------------------------------------------------------------
extern "C" void kernel_launch(void* const* d_in, const int* in_sizes, int n_in,
                              void* d_out, int out_size)
{
    const float* x  = (const float*)d_in[0];
    const float* c  = (const float*)d_in[1];
    const float* W1 = (const float*)d_in[2];
    const float* b1 = (const float*)d_in[3];
    const float* W2 = (const float*)d_in[4];
    const float* b2 = (const float*)d_in[5];
    const float* W3 = (const float*)d_in[6];
    const float* b3 = (const float*)d_in[7];
    const float* W4 = (const float*)d_in[8];
    float* out = (float*)d_out;

    const int B = in_sizes[0];   // 8192

    // 1) nearest neighbor -> g_c0
    {
        int threads = 256;
        int blocks  = (B + threads - 1) / threads;
        size_t smem = (size_t)B * sizeof(float);
        nn_kernel<<<blocks, threads, smem>>>(c, B);
    }

    // 2) warp-per-sample solve: 8 samples per 256-thread block
    {
        int blocks = (B + 7) / 8;   // 1024
        solve_kernel<<<blocks, 256>>>(x, W1, b1, W2, b2, W3, b3, W4, out, B);
    }
}